// round 8
// baseline (speedup 1.0000x reference)
#include <cuda_runtime.h>
#include <cuda_fp16.h>
#include <cstdint>

// Problem constants (B=8, S=8192, IN=OUT=1024)
#define TOKENS 65536
#define KDIM   1024
#define NDIM   1024

// GEMM tiling: CTA 128x128, 8 warps (2m x 4n), warp tile 64x32, mma m16n8k16 f16
#define BM 128
#define BN 128
#define BK 32
#define PAD_H 40                     // halves per smem row (80B)
#define NKITER (KDIM / BK)           // 32
#define STAGES 4
#define A_STRIDE (BM * PAD_H)
#define B_STRIDE (BN * PAD_H)
#define STAGE_H (A_STRIDE + B_STRIDE)

// ---------------------------------------------------------------------------
// Device scratch (static: allocation-free)
// ---------------------------------------------------------------------------
__device__ int g_cnt[2];
__device__ int g_mask_is_i32;
__device__ int g_rows[TOKENS];
__device__ int g_dst[TOKENS];
__device__ __align__(16) __half g_xh[(size_t)(TOKENS + 128) * KDIM];
__device__ __align__(16) __half g_wh[(size_t)2 * NDIM * KDIM];

__global__ void init_kernel(const uint32_t* __restrict__ mask32) {
    if (threadIdx.x == 0) {
        int is_i32 = 1;
        #pragma unroll 8
        for (int i = 0; i < 64; i++)
            if (mask32[i] > 1u) { is_i32 = 0; break; }
        g_mask_is_i32 = is_i32;
        g_cnt[0] = 0;
        g_cnt[1] = 0;
    }
}

__global__ void build_lists_kernel(const void* __restrict__ mask) {
    int i = blockIdx.x * blockDim.x + threadIdx.x;
    if (i < TOKENS) {
        int m = g_mask_is_i32 ? ((const int*)mask)[i]
                              : (int)((const unsigned char*)mask)[i];
        if (m) { int p = atomicAdd(&g_cnt[0], 1); g_dst[i] = p; }
        else   { int p = atomicAdd(&g_cnt[1], 1); g_dst[i] = ~p; }
    }
}

// launch-index shim so ncu (-s 5 -c 1) lands on the GEMM
__global__ void dummy_kernel() {}

// fp32 -> fp16 (rn) with k16-block permutation [2s,2s+1,2s+8,2s+9] -> [4s..4s+3]
__device__ __forceinline__ void cvt_permute8(const float4 v0, const float4 v1,
                                             __half out[8]) {
    out[0] = __float2half_rn(v0.x); out[1] = __float2half_rn(v0.y);
    out[2] = __float2half_rn(v1.x); out[3] = __float2half_rn(v1.y);
    out[4] = __float2half_rn(v0.z); out[5] = __float2half_rn(v0.w);
    out[6] = __float2half_rn(v1.z); out[7] = __float2half_rn(v1.w);
}

__global__ void __launch_bounds__(128) prep_x_kernel(const float* __restrict__ x) {
    const int tok = blockIdx.x;
    const int t = threadIdx.x;
    const int cv = g_cnt[0];
    const int d = g_dst[tok];
    const int row = (d >= 0) ? d : cv + ~d;
    if (t == 0) g_rows[row] = tok;
    const int blk = t >> 1, h = t & 1;
    const float* src = x + (size_t)tok * KDIM + blk * 16;
    const float4 v0 = *(const float4*)(src + 4 * h);
    const float4 v1 = *(const float4*)(src + 4 * h + 8);
    __half o[8];
    cvt_permute8(v0, v1, o);
    *(uint4*)(g_xh + (size_t)row * KDIM + blk * 16 + 8 * h) = *(const uint4*)o;
}

__global__ void __launch_bounds__(128) prep_w_kernel(const float* __restrict__ w_v,
                                                     const float* __restrict__ w_t) {
    const int r = blockIdx.x;
    const int t = threadIdx.x;
    const float* src_base = (r < NDIM) ? w_v : w_t;
    const int rr = (r < NDIM) ? r : r - NDIM;
    const int blk = t >> 1, h = t & 1;
    const float* src = src_base + (size_t)rr * KDIM + blk * 16;
    const float4 v0 = *(const float4*)(src + 4 * h);
    const float4 v1 = *(const float4*)(src + 4 * h + 8);
    __half o[8];
    cvt_permute8(v0, v1, o);
    *(uint4*)(g_wh + (size_t)r * KDIM + blk * 16 + 8 * h) = *(const uint4*)o;
}

__device__ __forceinline__ void cp_async16(uint32_t d, const void* s) {
    asm volatile("cp.async.cg.shared.global [%0], [%1], 16;" :: "r"(d), "l"(s));
}
#define CP_COMMIT() asm volatile("cp.async.commit_group;")

// ---------------------------------------------------------------------------
// Routed GEMM (fp16 MMA): grid = (8, 513); 256 threads, occ 2.
// 4-stage cp.async ring, 1 barrier/k-iter, fragment double-buffer inside iter.
// ---------------------------------------------------------------------------
__global__ void __launch_bounds__(256, 2) routed_gemm_kernel(float* __restrict__ out)
{
    extern __shared__ __half smem[];       // [STAGES][STAGE_H]
    __shared__ int rows_s[BM];

    const int cv = g_cnt[0];
    const int ct = g_cnt[1];
    const int vis_tiles = (cv + BM - 1) >> 7;

    const int tile = blockIdx.y;
    int row0, count_lim;
    const __half* W;
    if (tile < vis_tiles) {
        row0 = tile << 7;          count_lim = cv;       W = g_wh;
    } else {
        const int base = (tile - vis_tiles) << 7;
        if (base >= ct) return;
        row0 = cv + base;          count_lim = cv + ct;  W = g_wh + (size_t)NDIM * KDIM;
    }
    const int mvalid = min(BM, count_lim - row0);

    const int tid = threadIdx.x;
    if (tid < BM) rows_s[tid] = g_rows[min(row0 + tid, TOKENS - 1)];

    const int n_cta = blockIdx.x * BN;

    auto load_stage = [&](int kt) {
        const int s = kt & (STAGES - 1);
        const int k0 = kt * BK;
        __half* Ab = smem + s * STAGE_H;
        __half* Bb = Ab + A_STRIDE;
        #pragma unroll
        for (int i = 0; i < 2; i++) {
            const int idx = i * 256 + tid;
            const int r = idx >> 2, cg = idx & 3;
            uint32_t d = (uint32_t)__cvta_generic_to_shared(&Ab[r * PAD_H + cg * 8]);
            cp_async16(d, g_xh + (size_t)(row0 + r) * KDIM + k0 + cg * 8);
        }
        #pragma unroll
        for (int i = 0; i < 2; i++) {
            const int idx = i * 256 + tid;
            const int r = idx >> 2, cg = idx & 3;
            uint32_t d = (uint32_t)__cvta_generic_to_shared(&Bb[r * PAD_H + cg * 8]);
            cp_async16(d, W + (size_t)(n_cta + r) * KDIM + k0 + cg * 8);
        }
        CP_COMMIT();
    };

    const int lane = tid & 31;
    const int g  = lane >> 2;
    const int tg = lane & 3;
    const int wid = tid >> 5;
    const int m0  = (wid >> 2) * 64;
    const int n0w = (wid & 3) * 32;

    float acc[4][4][4];
    #pragma unroll
    for (int mt = 0; mt < 4; mt++)
        #pragma unroll
        for (int nt = 0; nt < 4; nt++)
            #pragma unroll
            for (int r = 0; r < 4; r++) acc[mt][nt][r] = 0.0f;

    load_stage(0);
    load_stage(1);
    load_stage(2);

    // fragment double-buffer
    uint2 a_lo[2][4], a_hi[2][4], bf[2][4];

    auto load_frags = [&](const __half* Ab, const __half* Bb, int ks, int buf) {
        const int co = ks * 16 + tg * 4;
        #pragma unroll
        for (int mt = 0; mt < 4; mt++) {
            const int r = m0 + mt * 16 + g;
            a_lo[buf][mt] = *(const uint2*)&Ab[r * PAD_H + co];
            a_hi[buf][mt] = *(const uint2*)&Ab[(r + 8) * PAD_H + co];
        }
        #pragma unroll
        for (int nt = 0; nt < 4; nt++) {
            const int n = n0w + nt * 8 + g;
            bf[buf][nt] = *(const uint2*)&Bb[n * PAD_H + co];
        }
    };

    auto mma_frags = [&](int buf) {
        #pragma unroll
        for (int mt = 0; mt < 4; mt++)
            #pragma unroll
            for (int nt = 0; nt < 4; nt++)
                asm volatile(
                    "mma.sync.aligned.m16n8k16.row.col.f32.f16.f16.f32 "
                    "{%0,%1,%2,%3}, {%4,%5,%6,%7}, {%8,%9}, {%0,%1,%2,%3};\n"
                    : "+f"(acc[mt][nt][0]), "+f"(acc[mt][nt][1]),
                      "+f"(acc[mt][nt][2]), "+f"(acc[mt][nt][3])
                    : "r"(a_lo[buf][mt].x), "r"(a_hi[buf][mt].x),
                      "r"(a_lo[buf][mt].y), "r"(a_hi[buf][mt].y),
                      "r"(bf[buf][nt].x),   "r"(bf[buf][nt].y));
    };

    for (int kt = 0; kt < NKITER; kt++) {
        asm volatile("cp.async.wait_group 2;");
        __syncthreads();

        if (kt + 3 < NKITER) load_stage(kt + 3);

        const int s = kt & (STAGES - 1);
        const __half* Ab = smem + s * STAGE_H;
        const __half* Bb = Ab + A_STRIDE;

        load_frags(Ab, Bb, 0, 0);      // ks=0 frags
        load_frags(Ab, Bb, 1, 1);      // ks=1 frags (overlap with ks=0 MMAs below)
        mma_frags(0);
        mma_frags(1);
    }

    // ---- epilogue: scatter float2 per fragment row
    #pragma unroll
    for (int mt = 0; mt < 4; mt++) {
        const int r_lo = m0 + mt * 16 + g;
        const int r_hi = r_lo + 8;
        const bool ok_lo = r_lo < mvalid;
        const bool ok_hi = r_hi < mvalid;
        float* row_lo = ok_lo ? out + (size_t)rows_s[r_lo] * NDIM + n_cta : nullptr;
        float* row_hi = ok_hi ? out + (size_t)rows_s[r_hi] * NDIM + n_cta : nullptr;
        #pragma unroll
        for (int nt = 0; nt < 4; nt++) {
            const int col = n0w + nt * 8 + tg * 2;
            if (ok_lo)
                *(float2*)(row_lo + col) = make_float2(acc[mt][nt][0], acc[mt][nt][1]);
            if (ok_hi)
                *(float2*)(row_hi + col) = make_float2(acc[mt][nt][2], acc[mt][nt][3]);
        }
    }
}

// ---------------------------------------------------------------------------
// Launch (graph-capturable). Launch order puts the GEMM at index 5 so the
// harness's ncu capture (-s 5 -c 1) profiles it.
// ---------------------------------------------------------------------------
extern "C" void kernel_launch(void* const* d_in, const int* in_sizes, int n_in,
                              void* d_out, int out_size)
{
    const float* x    = (const float*)d_in[0];
    const void*  mask = d_in[1];
    const float* w_v  = (const float*)d_in[2];
    const float* w_t  = (const float*)d_in[3];
    float*       out  = (float*)d_out;

    init_kernel<<<1, 32>>>((const uint32_t*)mask);        // launch 0
    build_lists_kernel<<<TOKENS / 256, 256>>>(mask);      // launch 1
    prep_x_kernel<<<TOKENS, 128>>>(x);                    // launch 2
    prep_w_kernel<<<2 * NDIM, 128>>>(w_v, w_t);           // launch 3
    dummy_kernel<<<1, 32>>>();                            // launch 4 (ncu shim)

    const size_t smem_bytes = (size_t)STAGES * STAGE_H * sizeof(__half); // 81920
    cudaFuncSetAttribute(routed_gemm_kernel,
                         cudaFuncAttributeMaxDynamicSharedMemorySize,
                         (int)smem_bytes);

    dim3 grid(NDIM / BN, 513);
    routed_gemm_kernel<<<grid, 256, smem_bytes>>>(out);   // launch 5 <- profiled
}

// round 9
// speedup vs baseline: 1.0173x; 1.0173x over previous
#include <cuda_runtime.h>
#include <cuda_fp16.h>
#include <cstdint>

// Problem constants (B=8, S=8192, IN=OUT=1024)
#define TOKENS 65536
#define KDIM   1024
#define NDIM   1024

// GEMM tiling: CTA 128x128, 8 warps (2m x 4n), warp tile 64x32, mma m16n8k16 f16
#define BM 128
#define BN 128
#define BK 32
#define PAD_H 40                     // halves per smem row (80B)
#define NKITER (KDIM / BK)           // 32
#define STAGES 4
#define A_STRIDE (BM * PAD_H)
#define B_STRIDE (BN * PAD_H)
#define STAGE_H (A_STRIDE + B_STRIDE)

// ---------------------------------------------------------------------------
// Device scratch (static: allocation-free)
// ---------------------------------------------------------------------------
__device__ int g_cnt[2];
__device__ int g_mask_is_i32;
__device__ int g_rows[TOKENS];
__device__ int g_dst[TOKENS];
__device__ __align__(16) __half g_xh[(size_t)(TOKENS + 128) * KDIM];
__device__ __align__(16) __half g_wh[(size_t)2 * NDIM * KDIM];

__global__ void init_kernel(const uint32_t* __restrict__ mask32) {
    if (threadIdx.x == 0) {
        int is_i32 = 1;
        #pragma unroll 8
        for (int i = 0; i < 64; i++)
            if (mask32[i] > 1u) { is_i32 = 0; break; }
        g_mask_is_i32 = is_i32;
        g_cnt[0] = 0;
        g_cnt[1] = 0;
    }
}

__global__ void build_lists_kernel(const void* __restrict__ mask) {
    int i = blockIdx.x * blockDim.x + threadIdx.x;
    if (i < TOKENS) {
        int m = g_mask_is_i32 ? ((const int*)mask)[i]
                              : (int)((const unsigned char*)mask)[i];
        if (m) { int p = atomicAdd(&g_cnt[0], 1); g_dst[i] = p; }
        else   { int p = atomicAdd(&g_cnt[1], 1); g_dst[i] = ~p; }
    }
}

// fp32 -> fp16 (rn) with k16-block permutation [2s,2s+1,2s+8,2s+9] -> [4s..4s+3]
__device__ __forceinline__ void cvt_permute8(const float4 v0, const float4 v1,
                                             __half out[8]) {
    out[0] = __float2half_rn(v0.x); out[1] = __float2half_rn(v0.y);
    out[2] = __float2half_rn(v1.x); out[3] = __float2half_rn(v1.y);
    out[4] = __float2half_rn(v0.z); out[5] = __float2half_rn(v0.w);
    out[6] = __float2half_rn(v1.z); out[7] = __float2half_rn(v1.w);
}

// Merged prep: blocks [0, TOKENS) gather+convert x rows into routed order;
// blocks [TOKENS, TOKENS+2*NDIM) convert w_v / w_t rows.
__global__ void __launch_bounds__(128) prep_kernel(const float* __restrict__ x,
                                                   const float* __restrict__ w_v,
                                                   const float* __restrict__ w_t) {
    const int b = blockIdx.x;
    const int t = threadIdx.x;
    const int blk = t >> 1, h = t & 1;

    const float* src;
    __half* dst;
    if (b < TOKENS) {
        const int cv = g_cnt[0];
        const int d = g_dst[b];
        const int row = (d >= 0) ? d : cv + ~d;
        if (t == 0) g_rows[row] = b;
        src = x + (size_t)b * KDIM;
        dst = g_xh + (size_t)row * KDIM;
    } else {
        const int r = b - TOKENS;                 // 0..2047
        const float* sb = (r < NDIM) ? w_v : w_t;
        const int rr = (r < NDIM) ? r : r - NDIM;
        src = sb + (size_t)rr * KDIM;
        dst = g_wh + (size_t)r * KDIM;
    }

    const float4 v0 = *(const float4*)(src + blk * 16 + 4 * h);
    const float4 v1 = *(const float4*)(src + blk * 16 + 4 * h + 8);
    __half o[8];
    cvt_permute8(v0, v1, o);
    *(uint4*)(dst + blk * 16 + 8 * h) = *(const uint4*)o;
}

__device__ __forceinline__ void cp_async16(uint32_t d, const void* s) {
    asm volatile("cp.async.cg.shared.global [%0], [%1], 16;" :: "r"(d), "l"(s));
}
#define CP_COMMIT() asm volatile("cp.async.commit_group;")

// ---------------------------------------------------------------------------
// Routed GEMM (fp16 MMA): grid = (8, 513); 256 threads, occ 2.
// 4-stage cp.async ring, ONE __syncthreads per k-iter (R7 structure).
// ---------------------------------------------------------------------------
__global__ void __launch_bounds__(256, 2) routed_gemm_kernel(float* __restrict__ out)
{
    extern __shared__ __half smem[];       // [STAGES][STAGE_H]
    __shared__ int rows_s[BM];

    const int cv = g_cnt[0];
    const int ct = g_cnt[1];
    const int vis_tiles = (cv + BM - 1) >> 7;

    const int tile = blockIdx.y;
    int row0, count_lim;
    const __half* W;
    if (tile < vis_tiles) {
        row0 = tile << 7;          count_lim = cv;       W = g_wh;
    } else {
        const int base = (tile - vis_tiles) << 7;
        if (base >= ct) return;
        row0 = cv + base;          count_lim = cv + ct;  W = g_wh + (size_t)NDIM * KDIM;
    }
    const int mvalid = min(BM, count_lim - row0);

    const int tid = threadIdx.x;
    if (tid < BM) rows_s[tid] = g_rows[min(row0 + tid, TOKENS - 1)];

    const int n_cta = blockIdx.x * BN;

    auto load_stage = [&](int kt) {
        const int s = kt & (STAGES - 1);
        const int k0 = kt * BK;
        __half* Ab = smem + s * STAGE_H;
        __half* Bb = Ab + A_STRIDE;
        #pragma unroll
        for (int i = 0; i < 2; i++) {
            const int idx = i * 256 + tid;
            const int r = idx >> 2, cg = idx & 3;
            uint32_t d = (uint32_t)__cvta_generic_to_shared(&Ab[r * PAD_H + cg * 8]);
            cp_async16(d, g_xh + (size_t)(row0 + r) * KDIM + k0 + cg * 8);
        }
        #pragma unroll
        for (int i = 0; i < 2; i++) {
            const int idx = i * 256 + tid;
            const int r = idx >> 2, cg = idx & 3;
            uint32_t d = (uint32_t)__cvta_generic_to_shared(&Bb[r * PAD_H + cg * 8]);
            cp_async16(d, W + (size_t)(n_cta + r) * KDIM + k0 + cg * 8);
        }
        CP_COMMIT();
    };

    const int lane = tid & 31;
    const int g  = lane >> 2;
    const int tg = lane & 3;
    const int wid = tid >> 5;
    const int m0  = (wid >> 2) * 64;
    const int n0w = (wid & 3) * 32;

    float acc[4][4][4];
    #pragma unroll
    for (int mt = 0; mt < 4; mt++)
        #pragma unroll
        for (int nt = 0; nt < 4; nt++)
            #pragma unroll
            for (int r = 0; r < 4; r++) acc[mt][nt][r] = 0.0f;

    load_stage(0);
    load_stage(1);
    load_stage(2);

    for (int kt = 0; kt < NKITER; kt++) {
        asm volatile("cp.async.wait_group 2;");
        __syncthreads();

        if (kt + 3 < NKITER) load_stage(kt + 3);

        const int s = kt & (STAGES - 1);
        const __half* Ab = smem + s * STAGE_H;
        const __half* Bb = Ab + A_STRIDE;

        #pragma unroll
        for (int ks = 0; ks < 2; ks++) {
            const int co = ks * 16 + tg * 4;
            uint2 a_lo[4], a_hi[4], b[4];
            #pragma unroll
            for (int mt = 0; mt < 4; mt++) {
                const int r = m0 + mt * 16 + g;
                a_lo[mt] = *(const uint2*)&Ab[r * PAD_H + co];
                a_hi[mt] = *(const uint2*)&Ab[(r + 8) * PAD_H + co];
            }
            #pragma unroll
            for (int nt = 0; nt < 4; nt++) {
                const int n = n0w + nt * 8 + g;
                b[nt] = *(const uint2*)&Bb[n * PAD_H + co];
            }
            #pragma unroll
            for (int mt = 0; mt < 4; mt++)
                #pragma unroll
                for (int nt = 0; nt < 4; nt++)
                    asm volatile(
                        "mma.sync.aligned.m16n8k16.row.col.f32.f16.f16.f32 "
                        "{%0,%1,%2,%3}, {%4,%5,%6,%7}, {%8,%9}, {%0,%1,%2,%3};\n"
                        : "+f"(acc[mt][nt][0]), "+f"(acc[mt][nt][1]),
                          "+f"(acc[mt][nt][2]), "+f"(acc[mt][nt][3])
                        : "r"(a_lo[mt].x), "r"(a_hi[mt].x),
                          "r"(a_lo[mt].y), "r"(a_hi[mt].y),
                          "r"(b[nt].x),    "r"(b[nt].y));
        }
    }

    // ---- epilogue: scatter float2 per fragment row
    #pragma unroll
    for (int mt = 0; mt < 4; mt++) {
        const int r_lo = m0 + mt * 16 + g;
        const int r_hi = r_lo + 8;
        const bool ok_lo = r_lo < mvalid;
        const bool ok_hi = r_hi < mvalid;
        float* row_lo = ok_lo ? out + (size_t)rows_s[r_lo] * NDIM + n_cta : nullptr;
        float* row_hi = ok_hi ? out + (size_t)rows_s[r_hi] * NDIM + n_cta : nullptr;
        #pragma unroll
        for (int nt = 0; nt < 4; nt++) {
            const int col = n0w + nt * 8 + tg * 2;
            if (ok_lo)
                *(float2*)(row_lo + col) = make_float2(acc[mt][nt][0], acc[mt][nt][1]);
            if (ok_hi)
                *(float2*)(row_hi + col) = make_float2(acc[mt][nt][2], acc[mt][nt][3]);
        }
    }
}

// ---------------------------------------------------------------------------
// Launch (graph-capturable). GEMM is my launch index 3: with the harness's 2
// internal launches, ncu's -s 5 -c 1 profiles global index 5 = the GEMM.
// ---------------------------------------------------------------------------
extern "C" void kernel_launch(void* const* d_in, const int* in_sizes, int n_in,
                              void* d_out, int out_size)
{
    const float* x    = (const float*)d_in[0];
    const void*  mask = d_in[1];
    const float* w_v  = (const float*)d_in[2];
    const float* w_t  = (const float*)d_in[3];
    float*       out  = (float*)d_out;

    init_kernel<<<1, 32>>>((const uint32_t*)mask);            // my launch 0
    build_lists_kernel<<<TOKENS / 256, 256>>>(mask);          // my launch 1
    prep_kernel<<<TOKENS + 2 * NDIM, 128>>>(x, w_v, w_t);     // my launch 2

    const size_t smem_bytes = (size_t)STAGES * STAGE_H * sizeof(__half); // 81920
    cudaFuncSetAttribute(routed_gemm_kernel,
                         cudaFuncAttributeMaxDynamicSharedMemorySize,
                         (int)smem_bytes);

    dim3 grid(NDIM / BN, 513);
    routed_gemm_kernel<<<grid, 256, smem_bytes>>>(out);       // my launch 3 <- profiled
}

// round 10
// speedup vs baseline: 1.0660x; 1.0478x over previous
#include <cuda_runtime.h>
#include <cuda_fp16.h>
#include <cstdint>

// Problem constants (B=8, S=8192, IN=OUT=1024)
#define TOKENS 65536
#define KDIM   1024
#define NDIM   1024

// GEMM tiling: CTA 128x128, 4 warps (2m x 2n), warp tile 64x64, mma m16n8k16 f16
#define BM 128
#define BN 128
#define BK 32
#define PAD_H 40                     // halves per smem row (80B)
#define NKITER (KDIM / BK)           // 32
#define STAGES 5
#define A_STRIDE (BM * PAD_H)
#define B_STRIDE (BN * PAD_H)
#define STAGE_H (A_STRIDE + B_STRIDE)
#define NTHREADS 128

// ---------------------------------------------------------------------------
// Device scratch (static: allocation-free)
// ---------------------------------------------------------------------------
__device__ int g_cnt[2];
__device__ int g_mask_is_i32;
__device__ int g_rows[TOKENS];
__device__ int g_dst[TOKENS];
__device__ __align__(16) __half g_xh[(size_t)(TOKENS + 128) * KDIM];
__device__ __align__(16) __half g_wh[(size_t)2 * NDIM * KDIM];

__global__ void init_kernel(const uint32_t* __restrict__ mask32) {
    if (threadIdx.x == 0) {
        int is_i32 = 1;
        #pragma unroll 8
        for (int i = 0; i < 64; i++)
            if (mask32[i] > 1u) { is_i32 = 0; break; }
        g_mask_is_i32 = is_i32;
        g_cnt[0] = 0;
        g_cnt[1] = 0;
    }
}

__global__ void build_lists_kernel(const void* __restrict__ mask) {
    int i = blockIdx.x * blockDim.x + threadIdx.x;
    if (i < TOKENS) {
        int m = g_mask_is_i32 ? ((const int*)mask)[i]
                              : (int)((const unsigned char*)mask)[i];
        if (m) { int p = atomicAdd(&g_cnt[0], 1); g_dst[i] = p; }
        else   { int p = atomicAdd(&g_cnt[1], 1); g_dst[i] = ~p; }
    }
}

// fp32 -> fp16 (rn) with k16-block permutation [2s,2s+1,2s+8,2s+9] -> [4s..4s+3]
__device__ __forceinline__ void cvt_permute8(const float4 v0, const float4 v1,
                                             __half out[8]) {
    out[0] = __float2half_rn(v0.x); out[1] = __float2half_rn(v0.y);
    out[2] = __float2half_rn(v1.x); out[3] = __float2half_rn(v1.y);
    out[4] = __float2half_rn(v0.z); out[5] = __float2half_rn(v0.w);
    out[6] = __float2half_rn(v1.z); out[7] = __float2half_rn(v1.w);
}

// Merged prep: blocks [0, TOKENS) gather+convert x rows into routed order;
// blocks [TOKENS, TOKENS+2*NDIM) convert w_v / w_t rows.
__global__ void __launch_bounds__(128) prep_kernel(const float* __restrict__ x,
                                                   const float* __restrict__ w_v,
                                                   const float* __restrict__ w_t) {
    const int b = blockIdx.x;
    const int t = threadIdx.x;
    const int blk = t >> 1, h = t & 1;

    const float* src;
    __half* dst;
    if (b < TOKENS) {
        const int cv = g_cnt[0];
        const int d = g_dst[b];
        const int row = (d >= 0) ? d : cv + ~d;
        if (t == 0) g_rows[row] = b;
        src = x + (size_t)b * KDIM;
        dst = g_xh + (size_t)row * KDIM;
    } else {
        const int r = b - TOKENS;
        const float* sb = (r < NDIM) ? w_v : w_t;
        const int rr = (r < NDIM) ? r : r - NDIM;
        src = sb + (size_t)rr * KDIM;
        dst = g_wh + (size_t)r * KDIM;
    }

    const float4 v0 = *(const float4*)(src + blk * 16 + 4 * h);
    const float4 v1 = *(const float4*)(src + blk * 16 + 4 * h + 8);
    __half o[8];
    cvt_permute8(v0, v1, o);
    *(uint4*)(dst + blk * 16 + 8 * h) = *(const uint4*)o;
}

__device__ __forceinline__ void cp_async16(uint32_t d, const void* s) {
    asm volatile("cp.async.cg.shared.global [%0], [%1], 16;" :: "r"(d), "l"(s));
}
#define CP_COMMIT() asm volatile("cp.async.commit_group;")

// ---------------------------------------------------------------------------
// Routed GEMM (fp16 MMA): grid = (8, 513); 128 threads (4 warps), occ 2.
// 5-stage cp.async ring, ONE __syncthreads per k-iter.
// Warp grid 2m x 2n, warp tile 64x64: A re-read x2, B re-read x2 (was x4/x2).
// ---------------------------------------------------------------------------
__global__ void __launch_bounds__(NTHREADS, 2) routed_gemm_kernel(float* __restrict__ out)
{
    extern __shared__ __half smem[];       // [STAGES][STAGE_H]
    __shared__ int rows_s[BM];

    const int cv = g_cnt[0];
    const int ct = g_cnt[1];
    const int vis_tiles = (cv + BM - 1) >> 7;

    const int tile = blockIdx.y;
    int row0, count_lim;
    const __half* W;
    if (tile < vis_tiles) {
        row0 = tile << 7;          count_lim = cv;       W = g_wh;
    } else {
        const int base = (tile - vis_tiles) << 7;
        if (base >= ct) return;
        row0 = cv + base;          count_lim = cv + ct;  W = g_wh + (size_t)NDIM * KDIM;
    }
    const int mvalid = min(BM, count_lim - row0);

    const int tid = threadIdx.x;
    rows_s[tid] = g_rows[min(row0 + tid, TOKENS - 1)];

    const int n_cta = blockIdx.x * BN;

    // per stage: A 512 x 16B chunks + B 512 x 16B chunks; 128 threads -> 4+4 each
    auto load_stage = [&](int kt) {
        const int s = kt % STAGES;
        const int k0 = kt * BK;
        __half* Ab = smem + s * STAGE_H;
        __half* Bb = Ab + A_STRIDE;
        #pragma unroll
        for (int i = 0; i < 4; i++) {
            const int idx = i * NTHREADS + tid;
            const int r = idx >> 2, cg = idx & 3;
            uint32_t d = (uint32_t)__cvta_generic_to_shared(&Ab[r * PAD_H + cg * 8]);
            cp_async16(d, g_xh + (size_t)(row0 + r) * KDIM + k0 + cg * 8);
        }
        #pragma unroll
        for (int i = 0; i < 4; i++) {
            const int idx = i * NTHREADS + tid;
            const int r = idx >> 2, cg = idx & 3;
            uint32_t d = (uint32_t)__cvta_generic_to_shared(&Bb[r * PAD_H + cg * 8]);
            cp_async16(d, W + (size_t)(n_cta + r) * KDIM + k0 + cg * 8);
        }
        CP_COMMIT();
    };

    const int lane = tid & 31;
    const int g  = lane >> 2;
    const int tg = lane & 3;
    const int wid = tid >> 5;
    const int m0  = (wid >> 1) * 64;   // 2 warps in m
    const int n0w = (wid & 1) * 64;    // 2 warps in n

    float acc[4][8][4];
    #pragma unroll
    for (int mt = 0; mt < 4; mt++)
        #pragma unroll
        for (int nt = 0; nt < 8; nt++)
            #pragma unroll
            for (int r = 0; r < 4; r++) acc[mt][nt][r] = 0.0f;

    load_stage(0);
    load_stage(1);
    load_stage(2);
    load_stage(3);

    for (int kt = 0; kt < NKITER; kt++) {
        asm volatile("cp.async.wait_group 3;");
        __syncthreads();               // stage kt visible; slot (kt-1)%5 free

        if (kt + 4 < NKITER) load_stage(kt + 4);

        const int s = kt % STAGES;
        const __half* Ab = smem + s * STAGE_H;
        const __half* Bb = Ab + A_STRIDE;

        #pragma unroll
        for (int ks = 0; ks < 2; ks++) {
            const int co = ks * 16 + tg * 4;
            uint2 a_lo[4], a_hi[4], b[8];
            #pragma unroll
            for (int mt = 0; mt < 4; mt++) {
                const int r = m0 + mt * 16 + g;
                a_lo[mt] = *(const uint2*)&Ab[r * PAD_H + co];
                a_hi[mt] = *(const uint2*)&Ab[(r + 8) * PAD_H + co];
            }
            #pragma unroll
            for (int nt = 0; nt < 8; nt++) {
                const int n = n0w + nt * 8 + g;
                b[nt] = *(const uint2*)&Bb[n * PAD_H + co];
            }
            #pragma unroll
            for (int mt = 0; mt < 4; mt++)
                #pragma unroll
                for (int nt = 0; nt < 8; nt++)
                    asm volatile(
                        "mma.sync.aligned.m16n8k16.row.col.f32.f16.f16.f32 "
                        "{%0,%1,%2,%3}, {%4,%5,%6,%7}, {%8,%9}, {%0,%1,%2,%3};\n"
                        : "+f"(acc[mt][nt][0]), "+f"(acc[mt][nt][1]),
                          "+f"(acc[mt][nt][2]), "+f"(acc[mt][nt][3])
                        : "r"(a_lo[mt].x), "r"(a_hi[mt].x),
                          "r"(a_lo[mt].y), "r"(a_hi[mt].y),
                          "r"(b[nt].x),    "r"(b[nt].y));
        }
    }

    // ---- epilogue: scatter float2 per fragment row
    #pragma unroll
    for (int mt = 0; mt < 4; mt++) {
        const int r_lo = m0 + mt * 16 + g;
        const int r_hi = r_lo + 8;
        const bool ok_lo = r_lo < mvalid;
        const bool ok_hi = r_hi < mvalid;
        float* row_lo = ok_lo ? out + (size_t)rows_s[r_lo] * NDIM + n_cta : nullptr;
        float* row_hi = ok_hi ? out + (size_t)rows_s[r_hi] * NDIM + n_cta : nullptr;
        #pragma unroll
        for (int nt = 0; nt < 8; nt++) {
            const int col = n0w + nt * 8 + tg * 2;
            if (ok_lo)
                *(float2*)(row_lo + col) = make_float2(acc[mt][nt][0], acc[mt][nt][1]);
            if (ok_hi)
                *(float2*)(row_hi + col) = make_float2(acc[mt][nt][2], acc[mt][nt][3]);
        }
    }
}

// ---------------------------------------------------------------------------
// Launch (graph-capturable). GEMM is my launch index 3 => profiled by ncu.
// ---------------------------------------------------------------------------
extern "C" void kernel_launch(void* const* d_in, const int* in_sizes, int n_in,
                              void* d_out, int out_size)
{
    const float* x    = (const float*)d_in[0];
    const void*  mask = d_in[1];
    const float* w_v  = (const float*)d_in[2];
    const float* w_t  = (const float*)d_in[3];
    float*       out  = (float*)d_out;

    init_kernel<<<1, 32>>>((const uint32_t*)mask);            // 0
    build_lists_kernel<<<TOKENS / 256, 256>>>(mask);          // 1
    prep_kernel<<<TOKENS + 2 * NDIM, 128>>>(x, w_v, w_t);     // 2

    const size_t smem_bytes = (size_t)STAGES * STAGE_H * sizeof(__half); // 81920
    cudaFuncSetAttribute(routed_gemm_kernel,
                         cudaFuncAttributeMaxDynamicSharedMemorySize,
                         (int)smem_bytes);

    dim3 grid(NDIM / BN, 513);
    routed_gemm_kernel<<<grid, NTHREADS, smem_bytes>>>(out);  // 3 <- profiled
}

// round 11
// speedup vs baseline: 1.0870x; 1.0197x over previous
#include <cuda_runtime.h>
#include <cuda_fp16.h>
#include <cstdint>

// Problem constants (B=8, S=8192, IN=OUT=1024)
#define TOKENS 65536
#define KDIM   1024
#define NDIM   1024

// GEMM tiling: CTA 96x128, 4 warps (2m x 2n), warp tile 48x64, mma m16n8k16 f16
#define BM 96
#define BN 128
#define BK 32
#define PAD_H 40                     // halves per smem row (80B)
#define NKITER (KDIM / BK)           // 32
#define STAGES 4
#define A_STRIDE (BM * PAD_H)        // 3840 halves
#define B_STRIDE (BN * PAD_H)        // 5120 halves
#define STAGE_H (A_STRIDE + B_STRIDE)
#define NTHREADS 128
#define MAX_TILES 684                // ceil(1/96)+ceil(65535/96)

// ---------------------------------------------------------------------------
// Device scratch (static: allocation-free)
// ---------------------------------------------------------------------------
__device__ int g_cnt[2];
__device__ int g_mask_is_i32;
__device__ int g_rows[TOKENS];
__device__ int g_dst[TOKENS];
__device__ __align__(16) __half g_xh[(size_t)(TOKENS + 128) * KDIM];
__device__ __align__(16) __half g_wh[(size_t)2 * NDIM * KDIM];

__global__ void init_kernel(const uint32_t* __restrict__ mask32) {
    if (threadIdx.x == 0) {
        int is_i32 = 1;
        #pragma unroll 8
        for (int i = 0; i < 64; i++)
            if (mask32[i] > 1u) { is_i32 = 0; break; }
        g_mask_is_i32 = is_i32;
        g_cnt[0] = 0;
        g_cnt[1] = 0;
    }
}

__global__ void build_lists_kernel(const void* __restrict__ mask) {
    int i = blockIdx.x * blockDim.x + threadIdx.x;
    if (i < TOKENS) {
        int m = g_mask_is_i32 ? ((const int*)mask)[i]
                              : (int)((const unsigned char*)mask)[i];
        if (m) { int p = atomicAdd(&g_cnt[0], 1); g_dst[i] = p; }
        else   { int p = atomicAdd(&g_cnt[1], 1); g_dst[i] = ~p; }
    }
}

// fp32 -> fp16 (rn) with k16-block permutation [2s,2s+1,2s+8,2s+9] -> [4s..4s+3]
__device__ __forceinline__ void cvt_permute8(const float4 v0, const float4 v1,
                                             __half out[8]) {
    out[0] = __float2half_rn(v0.x); out[1] = __float2half_rn(v0.y);
    out[2] = __float2half_rn(v1.x); out[3] = __float2half_rn(v1.y);
    out[4] = __float2half_rn(v0.z); out[5] = __float2half_rn(v0.w);
    out[6] = __float2half_rn(v1.z); out[7] = __float2half_rn(v1.w);
}

// Merged prep: blocks [0, TOKENS) gather+convert x rows into routed order;
// blocks [TOKENS, TOKENS+2*NDIM) convert w_v / w_t rows.
__global__ void __launch_bounds__(128) prep_kernel(const float* __restrict__ x,
                                                   const float* __restrict__ w_v,
                                                   const float* __restrict__ w_t) {
    const int b = blockIdx.x;
    const int t = threadIdx.x;
    const int blk = t >> 1, h = t & 1;

    const float* src;
    __half* dst;
    if (b < TOKENS) {
        const int cv = g_cnt[0];
        const int d = g_dst[b];
        const int row = (d >= 0) ? d : cv + ~d;
        if (t == 0) g_rows[row] = b;
        src = x + (size_t)b * KDIM;
        dst = g_xh + (size_t)row * KDIM;
    } else {
        const int r = b - TOKENS;
        const float* sb = (r < NDIM) ? w_v : w_t;
        const int rr = (r < NDIM) ? r : r - NDIM;
        src = sb + (size_t)rr * KDIM;
        dst = g_wh + (size_t)r * KDIM;
    }

    const float4 v0 = *(const float4*)(src + blk * 16 + 4 * h);
    const float4 v1 = *(const float4*)(src + blk * 16 + 4 * h + 8);
    __half o[8];
    cvt_permute8(v0, v1, o);
    *(uint4*)(dst + blk * 16 + 8 * h) = *(const uint4*)o;
}

__device__ __forceinline__ void cp_async16(uint32_t d, const void* s) {
    asm volatile("cp.async.cg.shared.global [%0], [%1], 16;" :: "r"(d), "l"(s));
}
#define CP_COMMIT() asm volatile("cp.async.commit_group;")

// ---------------------------------------------------------------------------
// Routed GEMM (fp16 MMA): grid = (8, 684); 128 threads (4 warps), occ 3.
// 4-stage cp.async ring, ONE __syncthreads per k-iter.
// Warp grid 2m x 2n, warp tile 48x64, acc 96 regs -> ~145 total -> 3 CTA/SM.
// ---------------------------------------------------------------------------
__global__ void __launch_bounds__(NTHREADS, 3) routed_gemm_kernel(float* __restrict__ out)
{
    extern __shared__ __half smem[];       // [STAGES][STAGE_H]
    __shared__ int rows_s[BM];

    const int cv = g_cnt[0];
    const int ct = g_cnt[1];
    const int vis_tiles = (cv + BM - 1) / BM;

    const int tile = blockIdx.y;
    int row0, count_lim;
    const __half* W;
    if (tile < vis_tiles) {
        row0 = tile * BM;          count_lim = cv;       W = g_wh;
    } else {
        const int base = (tile - vis_tiles) * BM;
        if (base >= ct) return;
        row0 = cv + base;          count_lim = cv + ct;  W = g_wh + (size_t)NDIM * KDIM;
    }
    const int mvalid = min(BM, count_lim - row0);

    const int tid = threadIdx.x;
    if (tid < BM) rows_s[tid] = g_rows[min(row0 + tid, TOKENS - 1)];

    const int n_cta = blockIdx.x * BN;

    // per stage: A 384 chunks (3 iters), B 512 chunks (4 iters); 16B each
    auto load_stage = [&](int kt) {
        const int s = kt & (STAGES - 1);
        const int k0 = kt * BK;
        __half* Ab = smem + s * STAGE_H;
        __half* Bb = Ab + A_STRIDE;
        #pragma unroll
        for (int i = 0; i < 3; i++) {
            const int idx = i * NTHREADS + tid;
            const int r = idx >> 2, cg = idx & 3;
            uint32_t d = (uint32_t)__cvta_generic_to_shared(&Ab[r * PAD_H + cg * 8]);
            cp_async16(d, g_xh + (size_t)(row0 + r) * KDIM + k0 + cg * 8);
        }
        #pragma unroll
        for (int i = 0; i < 4; i++) {
            const int idx = i * NTHREADS + tid;
            const int r = idx >> 2, cg = idx & 3;
            uint32_t d = (uint32_t)__cvta_generic_to_shared(&Bb[r * PAD_H + cg * 8]);
            cp_async16(d, W + (size_t)(n_cta + r) * KDIM + k0 + cg * 8);
        }
        CP_COMMIT();
    };

    const int lane = tid & 31;
    const int g  = lane >> 2;
    const int tg = lane & 3;
    const int wid = tid >> 5;
    const int m0  = (wid >> 1) * 48;   // 2 warps in m (48 rows each)
    const int n0w = (wid & 1) * 64;    // 2 warps in n (64 cols each)

    float acc[3][8][4];
    #pragma unroll
    for (int mt = 0; mt < 3; mt++)
        #pragma unroll
        for (int nt = 0; nt < 8; nt++)
            #pragma unroll
            for (int r = 0; r < 4; r++) acc[mt][nt][r] = 0.0f;

    load_stage(0);
    load_stage(1);
    load_stage(2);

    for (int kt = 0; kt < NKITER; kt++) {
        asm volatile("cp.async.wait_group 2;");
        __syncthreads();               // stage kt visible; slot (kt-1)%4 free

        if (kt + 3 < NKITER) load_stage(kt + 3);

        const int s = kt & (STAGES - 1);
        const __half* Ab = smem + s * STAGE_H;
        const __half* Bb = Ab + A_STRIDE;

        #pragma unroll
        for (int ks = 0; ks < 2; ks++) {
            const int co = ks * 16 + tg * 4;
            uint2 a_lo[3], a_hi[3], b[8];
            #pragma unroll
            for (int mt = 0; mt < 3; mt++) {
                const int r = m0 + mt * 16 + g;
                a_lo[mt] = *(const uint2*)&Ab[r * PAD_H + co];
                a_hi[mt] = *(const uint2*)&Ab[(r + 8) * PAD_H + co];
            }
            #pragma unroll
            for (int nt = 0; nt < 8; nt++) {
                const int n = n0w + nt * 8 + g;
                b[nt] = *(const uint2*)&Bb[n * PAD_H + co];
            }
            #pragma unroll
            for (int mt = 0; mt < 3; mt++)
                #pragma unroll
                for (int nt = 0; nt < 8; nt++)
                    asm volatile(
                        "mma.sync.aligned.m16n8k16.row.col.f32.f16.f16.f32 "
                        "{%0,%1,%2,%3}, {%4,%5,%6,%7}, {%8,%9}, {%0,%1,%2,%3};\n"
                        : "+f"(acc[mt][nt][0]), "+f"(acc[mt][nt][1]),
                          "+f"(acc[mt][nt][2]), "+f"(acc[mt][nt][3])
                        : "r"(a_lo[mt].x), "r"(a_hi[mt].x),
                          "r"(a_lo[mt].y), "r"(a_hi[mt].y),
                          "r"(b[nt].x),    "r"(b[nt].y));
        }
    }

    // ---- epilogue: scatter float2 per fragment row
    #pragma unroll
    for (int mt = 0; mt < 3; mt++) {
        const int r_lo = m0 + mt * 16 + g;
        const int r_hi = r_lo + 8;
        const bool ok_lo = r_lo < mvalid;
        const bool ok_hi = r_hi < mvalid;
        float* row_lo = ok_lo ? out + (size_t)rows_s[r_lo] * NDIM + n_cta : nullptr;
        float* row_hi = ok_hi ? out + (size_t)rows_s[r_hi] * NDIM + n_cta : nullptr;
        #pragma unroll
        for (int nt = 0; nt < 8; nt++) {
            const int col = n0w + nt * 8 + tg * 2;
            if (ok_lo)
                *(float2*)(row_lo + col) = make_float2(acc[mt][nt][0], acc[mt][nt][1]);
            if (ok_hi)
                *(float2*)(row_hi + col) = make_float2(acc[mt][nt][2], acc[mt][nt][3]);
        }
    }
}

// ---------------------------------------------------------------------------
// Launch (graph-capturable). GEMM is my launch index 3 => profiled by ncu.
// ---------------------------------------------------------------------------
extern "C" void kernel_launch(void* const* d_in, const int* in_sizes, int n_in,
                              void* d_out, int out_size)
{
    const float* x    = (const float*)d_in[0];
    const void*  mask = d_in[1];
    const float* w_v  = (const float*)d_in[2];
    const float* w_t  = (const float*)d_in[3];
    float*       out  = (float*)d_out;

    init_kernel<<<1, 32>>>((const uint32_t*)mask);            // 0
    build_lists_kernel<<<TOKENS / 256, 256>>>(mask);          // 1
    prep_kernel<<<TOKENS + 2 * NDIM, 128>>>(x, w_v, w_t);     // 2

    const size_t smem_bytes = (size_t)STAGES * STAGE_H * sizeof(__half); // 71680
    cudaFuncSetAttribute(routed_gemm_kernel,
                         cudaFuncAttributeMaxDynamicSharedMemorySize,
                         (int)smem_bytes);

    dim3 grid(NDIM / BN, MAX_TILES);
    routed_gemm_kernel<<<grid, NTHREADS, smem_bytes>>>(out);  // 3 <- profiled
}